// round 7
// baseline (speedup 1.0000x reference)
#include <cuda_runtime.h>

#define NH 18
#define NP 9
#define RW 20    // padded weight-row width (floats) = 80B -> rows 16B-aligned
#define BT 128   // threads per block

typedef unsigned long long u64;

// ---- smem float offsets ----
#define S_WF   0      // 6  rows x RW
#define S_WM   120    // 36 rows x RW
#define S_WUM  840    // 18 rows (Wu rows 0..17, message part)
#define S_WUH  1200   // 18 rows (Wu[18:36]+Wu[36:54] folded; U==h there)
#define S_WR   1560   // 5 rows x RW
#define S_BF   1660
#define S_BM   1680
#define S_BU   1700
#define S_BR   1720
#define S_H    1728   // h as DUPLICATED pairs: [ (node*18+e)*BT + tid ] of u64
                      // = 180*BT floats
#define S_TOTF (S_H + 180*BT)
#define SMEM_BYTES (S_TOTF * 4)            // 98,944 B -> dynamic smem attr

__device__ __forceinline__ u64 dup2(float v){
    u64 r; asm("mov.b64 %0, {%1,%1};" : "=l"(r) : "f"(v)); return r;
}
__device__ __forceinline__ u64 pk2(float lo, float hi){
    u64 r; asm("mov.b64 %0, {%1,%2};" : "=l"(r) : "f"(lo), "f"(hi)); return r;
}
__device__ __forceinline__ void upk2(u64 v, float& lo, float& hi){
    asm("mov.b64 {%0,%1}, %2;" : "=f"(lo), "=f"(hi) : "l"(v));
}
__device__ __forceinline__ u64 fma2(u64 a, u64 b, u64 c){
    u64 d; asm("fma.rn.f32x2 %0, %1, %2, %3;" : "=l"(d) : "l"(a), "l"(b), "l"(c));
    return d;
}
__device__ __forceinline__ float tanhap(float x){
    float r; asm("tanh.approx.f32 %0, %1;" : "=f"(r) : "f"(x)); return r;
}
// extract channel e (compile-time) from u64-pair accumulator array
__device__ __forceinline__ float getch(const u64* acc, int e){
    float lo, hi; upk2(acc[e >> 1], lo, hi);
    return (e & 1) ? hi : lo;
}

// 18-float weight row as 9 u64 pairs (broadcast, conflict-free)
__device__ __forceinline__ void ldrow9(const float* s, int off, u64 w[NP]){
    ulonglong2 q0 = *(const ulonglong2*)(s + off);
    ulonglong2 q1 = *(const ulonglong2*)(s + off + 4);
    ulonglong2 q2 = *(const ulonglong2*)(s + off + 8);
    ulonglong2 q3 = *(const ulonglong2*)(s + off + 12);
    w[0]=q0.x; w[1]=q0.y; w[2]=q1.x; w[3]=q1.y;
    w[4]=q2.x; w[5]=q2.y; w[6]=q3.x; w[7]=q3.y;
    w[8] = *(const u64*)(s + off + 16);
}

__global__ void __launch_bounds__(BT, 2) mp_kernel(
    const float* __restrict__ x,
    const float* __restrict__ Wf, const float* __restrict__ bf,
    const float* __restrict__ Wm, const float* __restrict__ bm,
    const float* __restrict__ Wu, const float* __restrict__ bu,
    const float* __restrict__ Wr, const float* __restrict__ br,
    float* __restrict__ out, int n)
{
    extern __shared__ __align__(16) float s[];
    const int t = threadIdx.x;
    for (int k = t; k < 6*NH;  k += BT){ int r=k/NH, c=k%NH; s[S_WF + r*RW + c] = Wf[k]; }
    for (int k = t; k < 36*NH; k += BT){ int r=k/NH, c=k%NH; s[S_WM + r*RW + c] = Wm[k]; }
    for (int k = t; k < 18*NH; k += BT){
        int r=k/NH, c=k%NH;
        s[S_WUM + r*RW + c] = Wu[k];
        s[S_WUH + r*RW + c] = Wu[324 + k] + Wu[648 + k];   // fold duplicated h columns
    }
    for (int k = t; k < 90; k += BT){ int r=k/NH, c=k%NH; s[S_WR + r*RW + c] = Wr[k]; }
    if (t < NH){ s[S_BF+t] = bf[t]; s[S_BM+t] = bm[t]; s[S_BU+t] = bu[t]; }
    if (t == 0) s[S_BR] = br[0];
    __syncthreads();

    const int b = blockIdx.x * BT + t;
    if (b >= n) return;

    // h stored as duplicated (v,v) u64 pairs, stride BT, per-thread slot t
    u64* H = (u64*)(s + S_H) + t;
    #define HS(i,e) H[((i)*NH + (e)) * BT]

    // ---- x[b]: 30 floats, 8B-aligned ----
    float xv[30];
    {
        const float2* xb = (const float2*)(x + (long long)b * 30);
        #pragma unroll
        for (int k = 0; k < 15; k++){ float2 v = xb[k]; xv[2*k]=v.x; xv[2*k+1]=v.y; }
    }

    // ======== layer 1: accL1_i = x_i @ Wf + bf  (RAW — no tanh burst) ========
    u64 accL1[5][NP];
    {
        u64 bb[NP]; ldrow9(s, S_BF, bb);
        #pragma unroll
        for (int p = 0; p < NP; p++){
            #pragma unroll
            for (int i = 0; i < 5; i++) accL1[i][p] = bb[p];
        }
        #pragma unroll
        for (int f = 0; f < 6; f++){
            u64 w[NP]; ldrow9(s, S_WF + f*RW, w);
            #pragma unroll
            for (int i = 0; i < 5; i++){
                u64 a = dup2(xv[i*6 + f]);
                #pragma unroll
                for (int p = 0; p < NP; p++) accL1[i][p] = fma2(a, w[p], accL1[i][p]);
            }
        }
    }

    // ======== layer M (e-fused, LAZY h conversion) ========
    // accM[i] = bm + sum_e Wm[e]*h_i[e] + Wm[18+e]*h_{i+1}[e]
    // h_i[e] = tanh(accL1_i[e]) computed inline (5 MUFU per e, hidden under 90 fma2),
    // stored to smem as (v,v) pair for the U layer.
    u64 accM[5][NP];
    {
        u64 bb[NP]; ldrow9(s, S_BM, bb);
        #pragma unroll
        for (int p = 0; p < NP; p++){
            #pragma unroll
            for (int i = 0; i < 5; i++) accM[i][p] = bb[p];
        }
        #pragma unroll
        for (int e = 0; e < NH; e++){
            u64 w1[NP]; ldrow9(s, S_WM + e*RW, w1);          // h_i part
            u64 w2[NP]; ldrow9(s, S_WM + (NH+e)*RW, w2);     // h_{i+1} part
            #pragma unroll
            for (int i = 0; i < 5; i++){
                float hv = tanhap(getch(accL1[i], e));       // lazy convert
                u64 a = dup2(hv);
                HS(i, e) = a;                                 // (v,v) for U layer
                #pragma unroll
                for (int p = 0; p < NP; p++) accM[i][p] = fma2(a, w1[p], accM[i][p]);
                const int j = (i + 4) % 5;                    // edge j has h_{j+1} = h_i
                #pragma unroll
                for (int p = 0; p < NP; p++) accM[j][p] = fma2(a, w2[p], accM[j][p]);
            }
        }
    }

    // ======== layer U (LAZY M conversion, h via dup'd LDS.64) ========
    // accU[i] = bu + sum_e WuM[e]*tanh(accM_{i-1}[e]) + WuH[e]*h_i[e]
    u64 accU[5][NP];
    {
        u64 bb[NP]; ldrow9(s, S_BU, bb);
        #pragma unroll
        for (int p = 0; p < NP; p++){
            #pragma unroll
            for (int i = 0; i < 5; i++) accU[i][p] = bb[p];
        }
        #pragma unroll
        for (int e = 0; e < NH; e++){
            u64 w1[NP]; ldrow9(s, S_WUM + e*RW, w1);
            u64 w2[NP]; ldrow9(s, S_WUH + e*RW, w2);
            #pragma unroll
            for (int i = 0; i < 5; i++){
                float mv = tanhap(getch(accM[(i+4)%5], e));  // lazy convert M_{i-1}
                u64 am = dup2(mv);
                #pragma unroll
                for (int p = 0; p < NP; p++) accU[i][p] = fma2(am, w1[p], accU[i][p]);
                u64 ah = HS(i, e);                            // (v,v) direct operand
                #pragma unroll
                for (int p = 0; p < NP; p++) accU[i][p] = fma2(ah, w2[p], accU[i][p]);
            }
        }
    }

    // ======== readout: out = sum_i tanh(accU_i) . Wr[i] + br ========
    // 5 parallel partial accumulators to shorten the dependency chain
    u64 rp[5];
    #pragma unroll
    for (int i = 0; i < 5; i++){
        u64 wr[NP]; ldrow9(s, S_WR + i*RW, wr);
        u64 racc = 0;
        #pragma unroll
        for (int p = 0; p < NP; p++){
            float lo, hi; upk2(accU[i][p], lo, hi);
            u64 u2 = pk2(tanhap(lo), tanhap(hi));
            racc = fma2(u2, wr[p], racc);
        }
        rp[i] = racc;
    }
    float r = s[S_BR];
    #pragma unroll
    for (int i = 0; i < 5; i++){
        float lo, hi; upk2(rp[i], lo, hi);
        r += lo + hi;
    }
    out[b] = r;
    #undef HS
}

extern "C" void kernel_launch(void* const* d_in, const int* in_sizes, int n_in,
                              void* d_out, int out_size)
{
    const float* x  = (const float*)d_in[0];
    const float* Wf = (const float*)d_in[1];
    const float* bf = (const float*)d_in[2];
    const float* Wm = (const float*)d_in[3];
    const float* bm = (const float*)d_in[4];
    const float* Wu = (const float*)d_in[5];
    const float* bu = (const float*)d_in[6];
    const float* Wr = (const float*)d_in[7];
    const float* br = (const float*)d_in[8];
    float* out = (float*)d_out;

    // >48KB dynamic smem: set attribute every call (idempotent, capture-safe)
    cudaFuncSetAttribute(mp_kernel, cudaFuncAttributeMaxDynamicSharedMemorySize,
                         SMEM_BYTES);

    const int n = in_sizes[0] / 30;     // B  (x is [B,5,6])
    const int blocks = (n + BT - 1) / BT;
    mp_kernel<<<blocks, BT, SMEM_BYTES>>>(x, Wf, bf, Wm, bm, Wu, bu, Wr, br, out, n);
}

// round 9
// speedup vs baseline: 1.2581x; 1.2581x over previous
#include <cuda_runtime.h>
#include <cuda_fp16.h>

typedef unsigned int u32;
typedef unsigned long long u64;

#define BT 128
#define ROWB 816                 // bytes per element row (mod 128 = 48: ldmatrix conflict-free)
// fp32 scalar region (float indices)
#define SF_WF 0                  // 6 x 20
#define SF_BF 120                // 20
#define SF_WR 140                // 5 x 24 (zero-padded)
#define SF_BM 260                // 24
#define SF_BU 284                // 24
#define SF_BR 308
// byte offsets
#define WMC_OFF 1248             // fp16 [48][24]  (M-layer B)
#define WUH_OFF (WMC_OFF + 2304) // fp16 [32][24]  (U-layer B, h part, folded)
#define WUM_OFF (WUH_OFF + 1536) // fp16 [32][24]  (U-layer B, message part)
#define ACT_OFF (WUM_OFF + 1536) // 6624, 16B aligned
#define SMEM_BYTES (ACT_OFF + BT*ROWB)   // 111072 -> 2 CTAs/SM
// per-row layout (bytes): 5 edge bufs @96 (h_i[18] pad6 h_{i+1}[18] pad6), then 5 M bufs @64
#define MB_OFF 480

static __device__ __forceinline__ u64 dup2(float v){
    u64 r; asm("mov.b64 %0, {%1,%1};" : "=l"(r) : "f"(v)); return r;
}
static __device__ __forceinline__ void upk2(u64 v, float& lo, float& hi){
    asm("mov.b64 {%0,%1}, %2;" : "=f"(lo), "=f"(hi) : "l"(v));
}
static __device__ __forceinline__ u64 fma2(u64 a, u64 b, u64 c){
    u64 d; asm("fma.rn.f32x2 %0, %1, %2, %3;" : "=l"(d) : "l"(a), "l"(b), "l"(c));
    return d;
}
static __device__ __forceinline__ float tanhap(float x){
    float r; asm("tanh.approx.f32 %0, %1;" : "=f"(r) : "f"(x)); return r;
}
static __device__ __forceinline__ void ldrow9(const float* s, int off, u64 w[9]){
    ulonglong2 q0 = *(const ulonglong2*)(s + off);
    ulonglong2 q1 = *(const ulonglong2*)(s + off + 4);
    ulonglong2 q2 = *(const ulonglong2*)(s + off + 8);
    ulonglong2 q3 = *(const ulonglong2*)(s + off + 12);
    w[0]=q0.x; w[1]=q0.y; w[2]=q1.x; w[3]=q1.y;
    w[4]=q2.x; w[5]=q2.y; w[6]=q3.x; w[7]=q3.y;
    w[8] = *(const u64*)(s + off + 16);
}
static __device__ __forceinline__ void ldm4(u32 addr, u32 a[4]){
    asm volatile("ldmatrix.sync.aligned.m8n8.x4.shared.b16 {%0,%1,%2,%3}, [%4];"
        : "=r"(a[0]),"=r"(a[1]),"=r"(a[2]),"=r"(a[3]) : "r"(addr));
}
static __device__ __forceinline__ void mmas(float d[4], const u32 a[4], const u32 b[2]){
    asm volatile("mma.sync.aligned.m16n8k16.row.col.f32.f16.f16.f32 "
        "{%0,%1,%2,%3}, {%4,%5,%6,%7}, {%8,%9}, {%0,%1,%2,%3};"
        : "+f"(d[0]),"+f"(d[1]),"+f"(d[2]),"+f"(d[3])
        : "r"(a[0]),"r"(a[1]),"r"(a[2]),"r"(a[3]), "r"(b[0]),"r"(b[1]));
}
// B fragment (m16n8k16 .col): reg0 = {B[k0][n], B[k0+1][n]}, reg1 = {B[k0+8][n], B[k0+9][n]}
static __device__ __forceinline__ void ldbfrag(const __half* W, int ks, int nf, int lane, u32 r[2]){
    int k0 = ks*16 + (lane & 3)*2;
    int nn = nf*8 + (lane >> 2);
    u32 a = __half_as_ushort(W[k0*24 + nn]);
    u32 b = __half_as_ushort(W[(k0+1)*24 + nn]);
    u32 c = __half_as_ushort(W[(k0+8)*24 + nn]);
    u32 d = __half_as_ushort(W[(k0+9)*24 + nn]);
    r[0] = a | (b << 16);
    r[1] = c | (d << 16);
}

__global__ void __launch_bounds__(BT, 2) mp_kernel(
    const float* __restrict__ x,
    const float* __restrict__ Wf, const float* __restrict__ bf,
    const float* __restrict__ Wm, const float* __restrict__ bm,
    const float* __restrict__ Wu, const float* __restrict__ bu,
    const float* __restrict__ Wr, const float* __restrict__ br,
    float* __restrict__ out, int n)
{
    extern __shared__ __align__(16) char smc[];
    float* sf = (float*)smc;
    const int t = threadIdx.x;

    // ---- zero activation region (pads must be finite-zero for mma) ----
    for (int i = t; i < (BT*ROWB)/16; i += BT)
        *(uint4*)(smc + ACT_OFF + i*16) = make_uint4(0,0,0,0);

    // ---- fp32 scalars ----
    for (int k = t; k < 120; k += BT){ int r=k/20, c=k%20; sf[SF_WF+k] = (c<18)? Wf[r*18+c] : 0.f; }
    for (int k = t; k < 20;  k += BT) sf[SF_BF+k] = (k<18)? bf[k] : 0.f;
    for (int k = t; k < 120; k += BT){ int r=k/24, c=k%24; sf[SF_WR+k] = (c<18)? Wr[r*18+c] : 0.f; }
    for (int k = t; k < 24;  k += BT){ sf[SF_BM+k] = (k<18)? bm[k] : 0.f;
                                       sf[SF_BU+k] = (k<18)? bu[k] : 0.f; }
    if (t == 0) sf[SF_BR] = br[0];

    // ---- fp16 B matrices ----
    for (int idx = t; idx < 48*24; idx += BT){
        int k = idx/24, nn = idx%24; float v = 0.f;
        if (nn < 18){
            if (k < 18) v = Wm[k*18 + nn];                    // h_i part
            else if (k >= 24 && k < 42) v = Wm[(k-6)*18 + nn];// h_{i+1} part (rows 18-35)
        }
        ((__half*)(smc + WMC_OFF))[idx] = __float2half(v);
    }
    for (int idx = t; idx < 32*24; idx += BT){
        int k = idx/24, nn = idx%24;
        float vh = 0.f, vm = 0.f;
        if (k < 18 && nn < 18){
            vh = Wu[(18+k)*18 + nn] + Wu[(36+k)*18 + nn];     // folded (U==h)
            vm = Wu[k*18 + nn];
        }
        ((__half*)(smc + WUH_OFF))[idx] = __float2half(vh);
        ((__half*)(smc + WUM_OFF))[idx] = __float2half(vm);
    }
    __syncthreads();

    // ================= layer 1: SIMT fp32, thread = element =================
    int e = blockIdx.x * BT + t;
    if (e >= n) e = n - 1;                    // clamp; no early return (warp-uniform mma later)
    {
        float xv[30];
        const float2* xb = (const float2*)(x + (long long)e * 30);
        #pragma unroll
        for (int k = 0; k < 15; k++){ float2 v = xb[k]; xv[2*k]=v.x; xv[2*k+1]=v.y; }

        u64 acc[5][9];
        {
            u64 bb[9]; ldrow9(sf, SF_BF, bb);
            #pragma unroll
            for (int p = 0; p < 9; p++){
                #pragma unroll
                for (int i = 0; i < 5; i++) acc[i][p] = bb[p];
            }
        }
        #pragma unroll
        for (int f = 0; f < 6; f++){
            u64 w[9]; ldrow9(sf, SF_WF + f*20, w);
            #pragma unroll
            for (int i = 0; i < 5; i++){
                u64 a = dup2(xv[i*6 + f]);
                #pragma unroll
                for (int p = 0; p < 9; p++) acc[i][p] = fma2(a, w[p], acc[i][p]);
            }
        }
        char* row = smc + ACT_OFF + t*ROWB;
        #pragma unroll
        for (int i = 0; i < 5; i++){
            u32 hp[9];
            #pragma unroll
            for (int p = 0; p < 9; p++){
                float lo, hi; upk2(acc[i][p], lo, hi);
                __half2 h2 = __floats2half2_rn(tanhap(lo), tanhap(hi));
                hp[p] = *(u32*)&h2;
            }
            uint4 q0 = make_uint4(hp[0],hp[1],hp[2],hp[3]);
            uint4 q1 = make_uint4(hp[4],hp[5],hp[6],hp[7]);
            // copy 1: edge i, h_i slot (offset 0)
            *(uint4*)(row + i*96)      = q0;
            *(uint4*)(row + i*96 + 16) = q1;
            *(u32*) (row + i*96 + 32)  = hp[8];
            // copy 2: edge (i-1), h_{i+1} slot (offset 48B = half 24)
            int j = (i + 4) % 5;
            *(uint4*)(row + j*96 + 48) = q0;
            *(uint4*)(row + j*96 + 64) = q1;
            *(u32*) (row + j*96 + 80)  = hp[8];
        }
    }
    __syncwarp();

    // ================= MMA phase: warp = 2 tiles of 16 elements =================
    const int lane = t & 31;
    const int w    = t >> 5;

    // B fragments (registers)
    u32 Bm[3][3][2], Bh[2][3][2], Bu2[2][3][2];
    {
        const __half* WMC = (const __half*)(smc + WMC_OFF);
        const __half* WUH = (const __half*)(smc + WUH_OFF);
        const __half* WUM = (const __half*)(smc + WUM_OFF);
        #pragma unroll
        for (int ks = 0; ks < 3; ks++)
            #pragma unroll
            for (int nf = 0; nf < 3; nf++) ldbfrag(WMC, ks, nf, lane, Bm[ks][nf]);
        #pragma unroll
        for (int ks = 0; ks < 2; ks++)
            #pragma unroll
            for (int nf = 0; nf < 3; nf++){
                ldbfrag(WUH, ks, nf, lane, Bh[ks][nf]);
                ldbfrag(WUM, ks, nf, lane, Bu2[ks][nf]);
            }
    }
    // bias pairs per n-fragment
    float bmv[3][2], buv[3][2];
    #pragma unroll
    for (int nf = 0; nf < 3; nf++){
        int c = nf*8 + (lane & 3)*2;
        bmv[nf][0] = sf[SF_BM + c]; bmv[nf][1] = sf[SF_BM + c + 1];
        buv[nf][0] = sf[SF_BU + c]; buv[nf][1] = sf[SF_BU + c + 1];
    }
    const float brv = sf[SF_BR];

    const u32 smem_base = (u32)__cvta_generic_to_shared(smc);
    const int lrow = lane & 15;
    const int lcol = (lane >> 4) << 4;     // byte offset within 16-col window

    #pragma unroll
    for (int tl = 0; tl < 2; tl++){
        const int rowbase = w*32 + tl*16;
        u32 tb = smem_base + ACT_OFF + rowbase*ROWB;
        u32 ab = tb + lrow*ROWB + lcol;            // edge-chain ldmatrix base
        u32 mb = tb + lrow*ROWB + MB_OFF + lcol;   // M-buffer ldmatrix base
        char* tgen = smc + ACT_OFF + rowbase*ROWB;

        // ---- M layer: M_i = tanh([h_i|h_{i+1}] @ Wm + bm) ----
        #pragma unroll
        for (int i = 0; i < 5; i++){
            u32 a0[4], a1[4], a2[4];
            ldm4(ab + i*96,      a0);
            ldm4(ab + i*96 + 32, a1);
            ldm4(ab + i*96 + 64, a2);
            float d[3][4];
            #pragma unroll
            for (int nf = 0; nf < 3; nf++){
                d[nf][0]=bmv[nf][0]; d[nf][1]=bmv[nf][1];
                d[nf][2]=bmv[nf][0]; d[nf][3]=bmv[nf][1];
                mmas(d[nf], a0, Bm[0][nf]);
                mmas(d[nf], a1, Bm[1][nf]);
                mmas(d[nf], a2, Bm[2][nf]);
            }
            char* dst = tgen + MB_OFF + ((i+1)%5)*64;
            int r = lane >> 2;
            #pragma unroll
            for (int nf = 0; nf < 3; nf++){
                int c = nf*8 + (lane & 3)*2;
                if (c < 18){
                    __half2 lo = __floats2half2_rn(tanhap(d[nf][0]), tanhap(d[nf][1]));
                    __half2 hi = __floats2half2_rn(tanhap(d[nf][2]), tanhap(d[nf][3]));
                    *(__half2*)(dst + r*ROWB + c*2)       = lo;
                    *(__half2*)(dst + (r+8)*ROWB + c*2)   = hi;
                }
            }
        }
        __syncwarp();

        // ---- U layer + readout ----
        float pr = 0.f, pr8 = 0.f;
        #pragma unroll
        for (int i = 0; i < 5; i++){
            u32 h0[4], h1[4], m0[4], m1[4];
            ldm4(ab + i*96,      h0);       // h_i window (cols 18-31: pad/garbage x zero-B)
            ldm4(ab + i*96 + 32, h1);
            ldm4(mb + i*64,      m0);       // M_{i-1}
            ldm4(mb + i*64 + 32, m1);
            float d[3][4];
            #pragma unroll
            for (int nf = 0; nf < 3; nf++){
                d[nf][0]=buv[nf][0]; d[nf][1]=buv[nf][1];
                d[nf][2]=buv[nf][0]; d[nf][3]=buv[nf][1];
                mmas(d[nf], h0, Bh[0][nf]);
                mmas(d[nf], h1, Bh[1][nf]);
                mmas(d[nf], m0, Bu2[0][nf]);
                mmas(d[nf], m1, Bu2[1][nf]);
            }
            #pragma unroll
            for (int nf = 0; nf < 3; nf++){
                int c = nf*8 + (lane & 3)*2;
                float w0 = sf[SF_WR + i*24 + c];
                float w1 = sf[SF_WR + i*24 + c + 1];
                pr  += tanhap(d[nf][0])*w0 + tanhap(d[nf][1])*w1;
                pr8 += tanhap(d[nf][2])*w0 + tanhap(d[nf][3])*w1;
            }
        }
        pr  += __shfl_xor_sync(0xffffffffu, pr, 1);
        pr  += __shfl_xor_sync(0xffffffffu, pr, 2);
        pr8 += __shfl_xor_sync(0xffffffffu, pr8, 1);
        pr8 += __shfl_xor_sync(0xffffffffu, pr8, 2);
        if ((lane & 3) == 0){
            int e0 = blockIdx.x * BT + rowbase + (lane >> 2);
            if (e0 < n)     out[e0]     = pr  + brv;
            if (e0 + 8 < n) out[e0 + 8] = pr8 + brv;
        }
        __syncwarp();
    }
}

extern "C" void kernel_launch(void* const* d_in, const int* in_sizes, int n_in,
                              void* d_out, int out_size)
{
    const float* x  = (const float*)d_in[0];
    const float* Wf = (const float*)d_in[1];
    const float* bf = (const float*)d_in[2];
    const float* Wm = (const float*)d_in[3];
    const float* bm = (const float*)d_in[4];
    const float* Wu = (const float*)d_in[5];
    const float* bu = (const float*)d_in[6];
    const float* Wr = (const float*)d_in[7];
    const float* br = (const float*)d_in[8];
    float* out = (float*)d_out;

    cudaFuncSetAttribute(mp_kernel, cudaFuncAttributeMaxDynamicSharedMemorySize,
                         SMEM_BYTES);

    const int n = in_sizes[0] / 30;     // B  (x is [B,5,6])
    const int blocks = (n + BT - 1) / BT;
    mp_kernel<<<blocks, BT, SMEM_BYTES>>>(x, Wf, bf, Wm, bm, Wu, bu, Wr, br, out, n);
}

// round 10
// speedup vs baseline: 1.9321x; 1.5358x over previous
#include <cuda_runtime.h>
#include <cuda_fp16.h>

typedef unsigned int u32;
typedef unsigned long long u64;

#define BT 128
#define ROWB 496                 // 496 mod 128 = 112 -> conflict-free ldmatrix
#define MSLOT 240                // M slots start in each element row
// fp32 scalar region (float indices)
#define SF_WF 0                  // 6 x 20
#define SF_BF 120                // 20
#define SF_WR 140                // 5 x 24 (zero-padded)
#define SF_BM 260                // 24
#define SF_BU 284                // 24
#define SF_BR 308
// fp16 B matrices, byte offsets ([32][24] each, zero rows 18-31)
#define WM1_OFF 1248
#define WM2_OFF (WM1_OFF + 1536)
#define WUH_OFF (WM2_OFF + 1536)
#define WUM_OFF (WUH_OFF + 1536)
#define ACT_OFF (WUM_OFF + 1536)          // 7392 (16B aligned)
#define SMEM_BYTES (ACT_OFF + BT*ROWB)    // 70880 -> 3 CTAs/SM

static __device__ __forceinline__ u64 dup2(float v){
    u64 r; asm("mov.b64 %0, {%1,%1};" : "=l"(r) : "f"(v)); return r;
}
static __device__ __forceinline__ void upk2(u64 v, float& lo, float& hi){
    asm("mov.b64 {%0,%1}, %2;" : "=f"(lo), "=f"(hi) : "l"(v));
}
static __device__ __forceinline__ u64 fma2(u64 a, u64 b, u64 c){
    u64 d; asm("fma.rn.f32x2 %0, %1, %2, %3;" : "=l"(d) : "l"(a), "l"(b), "l"(c));
    return d;
}
static __device__ __forceinline__ float tanhap(float x){
    float r; asm("tanh.approx.f32 %0, %1;" : "=f"(r) : "f"(x)); return r;
}
static __device__ __forceinline__ void ldrow9(const float* s, int off, u64 w[9]){
    ulonglong2 q0 = *(const ulonglong2*)(s + off);
    ulonglong2 q1 = *(const ulonglong2*)(s + off + 4);
    ulonglong2 q2 = *(const ulonglong2*)(s + off + 8);
    ulonglong2 q3 = *(const ulonglong2*)(s + off + 12);
    w[0]=q0.x; w[1]=q0.y; w[2]=q1.x; w[3]=q1.y;
    w[4]=q2.x; w[5]=q2.y; w[6]=q3.x; w[7]=q3.y;
    w[8] = *(const u64*)(s + off + 16);
}
static __device__ __forceinline__ void ldm4(u32 addr, u32 a[4]){
    asm volatile("ldmatrix.sync.aligned.m8n8.x4.shared.b16 {%0,%1,%2,%3}, [%4];"
        : "=r"(a[0]),"=r"(a[1]),"=r"(a[2]),"=r"(a[3]) : "r"(addr));
}
static __device__ __forceinline__ void mmas(float d[4], const u32 a[4], const u32 b[2]){
    asm volatile("mma.sync.aligned.m16n8k16.row.col.f32.f16.f16.f32 "
        "{%0,%1,%2,%3}, {%4,%5,%6,%7}, {%8,%9}, {%0,%1,%2,%3};"
        : "+f"(d[0]),"+f"(d[1]),"+f"(d[2]),"+f"(d[3])
        : "r"(a[0]),"r"(a[1]),"r"(a[2]),"r"(a[3]), "r"(b[0]),"r"(b[1]));
}
// B fragment (m16n8k16 .col): reg0={B[k0][n],B[k0+1][n]}, reg1={B[k0+8][n],B[k0+9][n]}
static __device__ __forceinline__ void ldbfrag(const __half* W, int ks, int nf, int lane, u32 r[2]){
    int k0 = ks*16 + (lane & 3)*2;
    int nn = nf*8 + (lane >> 2);
    u32 a = __half_as_ushort(W[k0*24 + nn]);
    u32 b = __half_as_ushort(W[(k0+1)*24 + nn]);
    u32 c = __half_as_ushort(W[(k0+8)*24 + nn]);
    u32 d = __half_as_ushort(W[(k0+9)*24 + nn]);
    r[0] = a | (b << 16);
    r[1] = c | (d << 16);
}

__global__ void __launch_bounds__(BT, 3) mp_kernel(
    const float* __restrict__ x,
    const float* __restrict__ Wf, const float* __restrict__ bf,
    const float* __restrict__ Wm, const float* __restrict__ bm,
    const float* __restrict__ Wu, const float* __restrict__ bu,
    const float* __restrict__ Wr, const float* __restrict__ br,
    float* __restrict__ out, int n)
{
    extern __shared__ __align__(16) char smc[];
    float* sf = (float*)smc;
    const int t = threadIdx.x;

    // ---- zero activation region (all pads MUST be zero for the mma path) ----
    for (int i = t; i < (BT*ROWB)/16; i += BT)
        *(uint4*)(smc + ACT_OFF + i*16) = make_uint4(0,0,0,0);

    // ---- fp32 scalars ----
    for (int k = t; k < 120; k += BT){ int r=k/20, c=k%20; sf[SF_WF+k] = (c<18)? Wf[r*18+c] : 0.f; }
    for (int k = t; k < 20;  k += BT) sf[SF_BF+k] = (k<18)? bf[k] : 0.f;
    for (int k = t; k < 120; k += BT){ int r=k/24, c=k%24; sf[SF_WR+k] = (c<18)? Wr[r*18+c] : 0.f; }
    for (int k = t; k < 24;  k += BT){ sf[SF_BM+k] = (k<18)? bm[k] : 0.f;
                                       sf[SF_BU+k] = (k<18)? bu[k] : 0.f; }
    if (t == 0) sf[SF_BR] = br[0];

    // ---- fp16 B matrices [32][24], rows 18-31 zero ----
    for (int idx = t; idx < 32*24; idx += BT){
        int k = idx/24, nn = idx%24;
        float v1=0.f, v2=0.f, vh=0.f, vm=0.f;
        if (k < 18 && nn < 18){
            v1 = Wm[k*18 + nn];                               // h_i part
            v2 = Wm[(18+k)*18 + nn];                          // h_{i+1} part
            vh = Wu[(18+k)*18 + nn] + Wu[(36+k)*18 + nn];     // folded (U==h)
            vm = Wu[k*18 + nn];
        }
        ((__half*)(smc + WM1_OFF))[idx] = __float2half(v1);
        ((__half*)(smc + WM2_OFF))[idx] = __float2half(v2);
        ((__half*)(smc + WUH_OFF))[idx] = __float2half(vh);
        ((__half*)(smc + WUM_OFF))[idx] = __float2half(vm);
    }
    __syncthreads();

    // ================= layer 1: SIMT fp32, thread = element =================
    int e = blockIdx.x * BT + t;
    if (e >= n) e = n - 1;                    // clamp; no early return (warp-collective mma later)
    {
        float xv[30];
        const float2* xb = (const float2*)(x + (long long)e * 30);
        #pragma unroll
        for (int k = 0; k < 15; k++){ float2 v = xb[k]; xv[2*k]=v.x; xv[2*k+1]=v.y; }

        u64 acc[5][9];
        {
            u64 bb[9]; ldrow9(sf, SF_BF, bb);
            #pragma unroll
            for (int p = 0; p < 9; p++){
                #pragma unroll
                for (int i = 0; i < 5; i++) acc[i][p] = bb[p];
            }
        }
        #pragma unroll
        for (int f = 0; f < 6; f++){
            u64 w[9]; ldrow9(sf, SF_WF + f*20, w);
            #pragma unroll
            for (int i = 0; i < 5; i++){
                u64 a = dup2(xv[i*6 + f]);
                #pragma unroll
                for (int p = 0; p < 9; p++) acc[i][p] = fma2(a, w[p], acc[i][p]);
            }
        }
        char* row = smc + ACT_OFF + t*ROWB;
        #pragma unroll
        for (int i = 0; i < 5; i++){
            u32 hp[9];
            #pragma unroll
            for (int p = 0; p < 9; p++){
                float lo, hi; upk2(acc[i][p], lo, hi);
                __half2 h2 = __floats2half2_rn(tanhap(lo), tanhap(hi));
                hp[p] = *(u32*)&h2;
            }
            *(uint4*)(row + i*48)      = make_uint4(hp[0],hp[1],hp[2],hp[3]);
            *(uint4*)(row + i*48 + 16) = make_uint4(hp[4],hp[5],hp[6],hp[7]);
            *(u32*) (row + i*48 + 32)  = hp[8];
        }
    }
    __syncwarp();

    // ================= MMA phase: warp = 2 tiles of 16 elements =================
    const int lane = t & 31;
    const int w    = t >> 5;

    // B fragments: 2 k-chunks x 3 n-frags each
    u32 Bm1[2][3][2], Bm2[2][3][2], Bh[2][3][2], Bu2[2][3][2];
    {
        const __half* W1 = (const __half*)(smc + WM1_OFF);
        const __half* W2 = (const __half*)(smc + WM2_OFF);
        const __half* WH = (const __half*)(smc + WUH_OFF);
        const __half* WM = (const __half*)(smc + WUM_OFF);
        #pragma unroll
        for (int ks = 0; ks < 2; ks++)
            #pragma unroll
            for (int nf = 0; nf < 3; nf++){
                ldbfrag(W1, ks, nf, lane, Bm1[ks][nf]);
                ldbfrag(W2, ks, nf, lane, Bm2[ks][nf]);
                ldbfrag(WH, ks, nf, lane, Bh[ks][nf]);
                ldbfrag(WM, ks, nf, lane, Bu2[ks][nf]);
            }
    }
    // bias pairs per n-fragment
    float bmv[3][2], buv[3][2];
    #pragma unroll
    for (int nf = 0; nf < 3; nf++){
        int c = nf*8 + (lane & 3)*2;
        bmv[nf][0] = sf[SF_BM + c]; bmv[nf][1] = sf[SF_BM + c + 1];
        buv[nf][0] = sf[SF_BU + c]; buv[nf][1] = sf[SF_BU + c + 1];
    }
    const float brv = sf[SF_BR];

    const u32 smem_base = (u32)__cvta_generic_to_shared(smc);
    const int lrow = lane & 15;
    const int lcol = (lane >> 4) << 4;     // 16B col window select

    #pragma unroll
    for (int tl = 0; tl < 2; tl++){
        const int rowbase = w*32 + tl*16;
        u32 ab = smem_base + ACT_OFF + rowbase*ROWB + lrow*ROWB + lcol;
        char* tgen = smc + ACT_OFF + rowbase*ROWB;

        // ---- M layer: M_i = tanh(h_i @ Wm1 + h_{i+1} @ Wm2 + bm) -> M slot (i+1) ----
        #pragma unroll
        for (int i = 0; i < 5; i++){
            const int ip = (i + 1) % 5;
            u32 a0[4], a1[4], b0[4], b1[4];
            ldm4(ab + i*48,       a0);     // h_i   k0-15
            ldm4(ab + i*48  + 32, a1);     // h_i   k16-31 (pad/overrun x zero B rows)
            ldm4(ab + ip*48,      b0);     // h_{i+1}
            ldm4(ab + ip*48 + 32, b1);
            float d[3][4];
            #pragma unroll
            for (int nf = 0; nf < 3; nf++){
                d[nf][0]=bmv[nf][0]; d[nf][1]=bmv[nf][1];
                d[nf][2]=bmv[nf][0]; d[nf][3]=bmv[nf][1];
                mmas(d[nf], a0, Bm1[0][nf]);
                mmas(d[nf], a1, Bm1[1][nf]);
                mmas(d[nf], b0, Bm2[0][nf]);
                mmas(d[nf], b1, Bm2[1][nf]);
            }
            char* dst = tgen + MSLOT + ip*48;
            int r = lane >> 2;
            #pragma unroll
            for (int nf = 0; nf < 3; nf++){
                int c = nf*8 + (lane & 3)*2;
                if (c < 18){
                    __half2 lo = __floats2half2_rn(tanhap(d[nf][0]), tanhap(d[nf][1]));
                    __half2 hi = __floats2half2_rn(tanhap(d[nf][2]), tanhap(d[nf][3]));
                    *(__half2*)(dst + r*ROWB + c*2)     = lo;
                    *(__half2*)(dst + (r+8)*ROWB + c*2) = hi;
                }
            }
        }
        __syncwarp();

        // ---- U layer + readout: U_i = tanh(M_{i-1}@WuM + h_i@WuH + bu) ----
        float pr = 0.f, pr8 = 0.f;
        #pragma unroll
        for (int i = 0; i < 5; i++){
            u32 h0[4], h1[4], m0[4], m1[4];
            ldm4(ab + i*48,              h0);
            ldm4(ab + i*48 + 32,         h1);
            ldm4(ab + MSLOT + i*48,      m0);   // M slot i holds M_{i-1}
            ldm4(ab + MSLOT + i*48 + 32, m1);
            float d[3][4];
            #pragma unroll
            for (int nf = 0; nf < 3; nf++){
                d[nf][0]=buv[nf][0]; d[nf][1]=buv[nf][1];
                d[nf][2]=buv[nf][0]; d[nf][3]=buv[nf][1];
                mmas(d[nf], h0, Bh[0][nf]);
                mmas(d[nf], h1, Bh[1][nf]);
                mmas(d[nf], m0, Bu2[0][nf]);
                mmas(d[nf], m1, Bu2[1][nf]);
            }
            #pragma unroll
            for (int nf = 0; nf < 3; nf++){
                int c = nf*8 + (lane & 3)*2;
                float w0 = sf[SF_WR + i*24 + c];
                float w1 = sf[SF_WR + i*24 + c + 1];
                pr  += tanhap(d[nf][0])*w0 + tanhap(d[nf][1])*w1;
                pr8 += tanhap(d[nf][2])*w0 + tanhap(d[nf][3])*w1;
            }
        }
        pr  += __shfl_xor_sync(0xffffffffu, pr, 1);
        pr  += __shfl_xor_sync(0xffffffffu, pr, 2);
        pr8 += __shfl_xor_sync(0xffffffffu, pr8, 1);
        pr8 += __shfl_xor_sync(0xffffffffu, pr8, 2);
        if ((lane & 3) == 0){
            int e0 = blockIdx.x * BT + rowbase + (lane >> 2);
            if (e0 < n)     out[e0]     = pr  + brv;
            if (e0 + 8 < n) out[e0 + 8] = pr8 + brv;
        }
        __syncwarp();
    }
}

extern "C" void kernel_launch(void* const* d_in, const int* in_sizes, int n_in,
                              void* d_out, int out_size)
{
    const float* x  = (const float*)d_in[0];
    const float* Wf = (const float*)d_in[1];
    const float* bf = (const float*)d_in[2];
    const float* Wm = (const float*)d_in[3];
    const float* bm = (const float*)d_in[4];
    const float* Wu = (const float*)d_in[5];
    const float* bu = (const float*)d_in[6];
    const float* Wr = (const float*)d_in[7];
    const float* br = (const float*)d_in[8];
    float* out = (float*)d_out;

    cudaFuncSetAttribute(mp_kernel, cudaFuncAttributeMaxDynamicSharedMemorySize,
                         SMEM_BYTES);

    const int n = in_sizes[0] / 30;     // B  (x is [B,5,6])
    const int blocks = (n + BT - 1) / BT;
    mp_kernel<<<blocks, BT, SMEM_BYTES>>>(x, Wf, bf, Wm, bm, Wu, bu, Wr, br, out, n);
}